// round 14
// baseline (speedup 1.0000x reference)
#include <cuda_runtime.h>
#include <cstdint>

#define NB 32        // batch
#define NS 8192      // seq len
#define ND 32        // hidden dim
#define NG 128       // 4*ND gates
#define NC 256       // output cats
#define CHUNK 32     // steps per progress publish
#define NCHUNK (NS / CHUNK)        // 256
#define NWORK 116                  // worker blocks (148 - 32)
#define NITEM (NB * NCHUNK)        // 8192 work items
#define NT 160                     // threads per block
#define ROWB (ND * 4)              // 128 bytes per ring row
#define HALFB (CHUNK * ROWB)       // 4096 bytes per ring half

// h history (B, S, D) fp32 = 33.5 MB + progress flags
__device__ float g_hs[NB * NS * ND];
__device__ int   g_prog[NB];

__device__ __forceinline__ float tanh_fast(float x) {
    float y;
    asm("tanh.approx.f32 %0, %1;" : "=f"(y) : "f"(x));
    return y;
}
__device__ __forceinline__ uint64_t pack2(float lo, float hi) {
    uint64_t r;
    asm("mov.b64 %0, {%1, %2};" : "=l"(r) : "f"(lo), "f"(hi));
    return r;
}
__device__ __forceinline__ void unpack2(float& lo, float& hi, uint64_t v) {
    asm("mov.b64 {%0, %1}, %2;" : "=f"(lo), "=f"(hi) : "l"(v));
}
__device__ __forceinline__ void fma2(uint64_t& acc, uint64_t a, uint64_t b) {
    asm("fma.rn.f32x2 %0, %1, %2, %0;" : "+l"(acc) : "l"(a), "l"(b));
}
__device__ __forceinline__ uint64_t add2(uint64_t a, uint64_t b) {
    uint64_t r;
    asm("add.rn.f32x2 %0, %1, %2;" : "=l"(r) : "l"(a), "l"(b));
    return r;
}
__device__ __forceinline__ void bar_sync(int id, int cnt) {
    asm volatile("bar.sync %0, %1;" :: "r"(id), "r"(cnt) : "memory");
}
__device__ __forceinline__ uint32_t smem_u32(const void* p) {
    uint32_t a;
    asm("{ .reg .u64 t; cvta.to.shared.u64 t, %1; cvt.u32.u64 %0, t; }"
        : "=r"(a) : "l"(p));
    return a;
}
__device__ __forceinline__ void publish(uint32_t addr, float act, int tag) {
    asm volatile("st.volatile.shared.v2.b32 [%0], {%1, %2};"
                 :: "r"(addr), "f"(act), "r"(tag) : "memory");
}

__global__ void init_kernel() {
    if (threadIdx.x < NB) g_prog[threadIdx.x] = 0;
}

// grid = 148 x 160.
//   blocks 0..31: LSTM scan. Warps 0-3 = gates (i,f,g,o), lane = hidden dim.
//     NO per-step barrier: activations exchanged as {act, step-tag} 8-byte
//     volatile smem slots, double-buffered by step parity; consumers poll
//     until all 4 tags match (data flow itself bounds skew to 1 step, which
//     makes parity reuse safe). Warp 0's 64-slot h ring feeds the mover
//     (warp 4), synced once per 32-step chunk via named bar 2 (64 thr).
//   blocks 32..147: persistent epilogue workers.
__global__ void __launch_bounds__(NT, 1) fused_kernel(
    const float* __restrict__ x,      // (B, S)
    const float* __restrict__ bos,    // (D)
    const float* __restrict__ W_in,   // (1, D)
    const float* __restrict__ b_in,   // (D)
    const float* __restrict__ Wx,     // (D, 4D)
    const float* __restrict__ Wh,     // (D, 4D)
    const float* __restrict__ b_lstm, // (4D)
    const float* __restrict__ W_out,  // (D, C)
    const float* __restrict__ b_out,  // (C)
    float* __restrict__ out)          // (B, S, C)
{
    const int bid = blockIdx.x;
    const int tid = threadIdx.x;

    if (bid < NB) {
        // ───────────────────────── scan block ─────────────────────────
        const int b = bid;

        __shared__ uint64_t gslot[2][4][32];   // [parity][gate][lane]={act,tag} 2KB
        __shared__ float    rings[4][64][ND];  // per-warp h rings            32KB

        if (tid < 128) {
            // ── scan warps ──
            const int w = tid >> 5;     // gate: 0=i 1=f 2=g 3=o
            const int l = tid & 31;     // hidden dim
            const int k = tid;          // gate column
            const bool sig = (w != 2);

            const float ws = sig ? 0.5f : 1.0f;
            uint64_t whp[16];
#pragma unroll
            for (int j = 0; j < 16; j++)
                whp[j] = pack2(ws * Wh[(2 * j) * NG + k],
                               ws * Wh[(2 * j + 1) * NG + k]);

            float u = 0.f, v = 0.f, z0 = 0.f;
#pragma unroll
            for (int d = 0; d < ND; d++) {
                float wx = Wx[d * NG + k];
                u  = fmaf(W_in[d], wx, u);
                v  = fmaf(b_in[d], wx, v);
                z0 = fmaf(bos[d],  wx, z0);
            }
            float bl = b_lstm[k];
            v  = ws * (v + bl);
            z0 = ws * (z0 + bl);
            u *= ws;

            const uint32_t ringw = smem_u32(&rings[w][0][0]);
            const uint32_t gb0   = smem_u32(gslot) + (uint32_t)l * 8;  // parity 0
            const uint32_t gb1   = gb0 + 1024;                         // parity 1
            const uint32_t own0  = gb0 + (uint32_t)w * 256;
            const uint32_t own1  = gb1 + (uint32_t)w * 256;

            // sentinel tag in parity-1 slot; act(0) into parity-0 slot
            publish(own1, 0.f, -1);
            {
                float t0 = tanh_fast(z0);
                float a0 = sig ? fmaf(0.5f, t0, 0.5f) : t0;
                publish(own0, a0, 0);
            }
            bar_sync(1, 128);          // sentinels + act(0) visible to all

            float c = 0.f;
            const float* xb = x + (size_t)b * NS;
            float xv_cur = __ldg(xb + l);           // chunk 0's x

            // J2 = compile-time step-in-group; runtime adds hoisted per group
#define STEP(J2) do {                                                        \
        const int s_ = sj + (J2);                                            \
        float xn = __shfl_sync(0xffffffffu, xv, jj + (J2));                  \
        float zbase = fmaf(xn, u, v);                                        \
        const uint32_t pa = (((J2) & 1) ? gb1 : gb0);                        \
        float i_, f_, g_, o_;                                                \
        uint32_t t0, t1, t2, t3;                                             \
        for (;;) {                                                           \
            asm volatile("ld.volatile.shared.v2.b32 {%0,%1}, [%2];"          \
                         : "=f"(i_), "=r"(t0) : "r"(pa + 0) : "memory");     \
            asm volatile("ld.volatile.shared.v2.b32 {%0,%1}, [%2];"          \
                         : "=f"(f_), "=r"(t1) : "r"(pa + 256) : "memory");   \
            asm volatile("ld.volatile.shared.v2.b32 {%0,%1}, [%2];"          \
                         : "=f"(g_), "=r"(t2) : "r"(pa + 512) : "memory");   \
            asm volatile("ld.volatile.shared.v2.b32 {%0,%1}, [%2];"          \
                         : "=f"(o_), "=r"(t3) : "r"(pa + 768) : "memory");   \
            int ok = (t0 == (uint32_t)s_) & (t1 == (uint32_t)s_) &           \
                     (t2 == (uint32_t)s_) & (t3 == (uint32_t)s_);            \
            if (__all_sync(0xffffffffu, ok)) break;                          \
        }                                                                    \
        c = fmaf(f_, c, i_ * g_);                                            \
        float h = o_ * tanh_fast(c);                                         \
        const uint32_t hrow = rbj + (J2) * ROWB;                             \
        asm volatile("st.shared.f32 [%0], %1;"                               \
                     :: "r"(hrow + l * 4), "f"(h) : "memory");               \
        uint64_t hp[16];                                                     \
        _Pragma("unroll")                                                    \
        for (int j = 0; j < 8; j++)                                          \
            asm volatile("ld.shared.v2.u64 {%0,%1}, [%2];"                   \
                         : "=l"(hp[2 * j]), "=l"(hp[2 * j + 1])              \
                         : "r"(hrow + j * 16));                              \
        uint64_t a0 = pack2(zbase, 0.f), a1 = pack2(0.f, 0.f);               \
        uint64_t a2 = pack2(0.f, 0.f),   a3 = pack2(0.f, 0.f);               \
        _Pragma("unroll")                                                    \
        for (int j = 0; j < 4; j++) {                                        \
            fma2(a0, hp[4 * j + 0], whp[4 * j + 0]);                         \
            fma2(a1, hp[4 * j + 1], whp[4 * j + 1]);                         \
            fma2(a2, hp[4 * j + 2], whp[4 * j + 2]);                         \
            fma2(a3, hp[4 * j + 3], whp[4 * j + 3]);                         \
        }                                                                    \
        float lo, hi;                                                        \
        unpack2(lo, hi, add2(add2(a0, a1), add2(a2, a3)));                   \
        float z = lo + hi;                                                   \
        float t = tanh_fast(z);                                              \
        float act = sig ? fmaf(0.5f, t, 0.5f) : t;                           \
        publish(((J2) & 1) ? own0 : own1, act, s_ + 1);                      \
    } while (0)

            for (int n = 0; n < NCHUNK; n++) {
                const uint32_t rb = ringw + (uint32_t)(n & 1) * HALFB;
                const int s0 = n * CHUNK;
                const float xv = xv_cur;
                xv_cur = __ldg(xb + ((n + 1) & (NCHUNK - 1)) * CHUNK + l);
#pragma unroll 1
                for (int jj = 0; jj < CHUNK; jj += 8) {
                    const int      sj  = s0 + jj;
                    const uint32_t rbj = rb + (uint32_t)jj * ROWB;
                    STEP(0); STEP(1); STEP(2); STEP(3);
                    STEP(4); STEP(5); STEP(6); STEP(7);
                }
                if (w == 0) bar_sync(2, 64);     // hand chunk n to mover
            }
#undef STEP
        } else {
            // ── mover warp (warp 4) ──
            const int l = tid - 128;
            float* hs_b = g_hs + (size_t)b * NS * ND;

            for (int n = 0; n < NCHUNK; n++) {
                bar_sync(2, 64);                 // wait: warp 0 finished chunk n
                const float4* src =
                    (const float4*)&rings[0][(n & 1) * CHUNK][0];
                float4* dst = (float4*)(hs_b + (size_t)n * CHUNK * ND);
#pragma unroll
                for (int q = 0; q < 8; q++)
                    dst[l + 32 * q] = src[l + 32 * q];
                if (l == 0) {
                    __threadfence();
                    asm volatile("st.global.release.gpu.s32 [%0], %1;"
                                 :: "l"(&g_prog[b]), "r"(n + 1) : "memory");
                }
            }
        }
    } else {
        // ─────────────────────── worker block ───────────────────────
        const int wkr = bid - NB;
        __shared__ float tile[CHUNK * ND];       // 4 KB h tile

        const int c0 = tid, c1 = tid + 128;      // valid for tid < 128
        uint64_t wv0[16], wv1[16];
        float bias0 = 0.f, bias1 = 0.f;
        if (tid < 128) {
#pragma unroll
            for (int j = 0; j < 16; j++) {
                wv0[j] = pack2(W_out[(2 * j) * NC + c0], W_out[(2 * j + 1) * NC + c0]);
                wv1[j] = pack2(W_out[(2 * j) * NC + c1], W_out[(2 * j + 1) * NC + c1]);
            }
            bias0 = b_out[c0];
            bias1 = b_out[c1];
        }

        for (int i = wkr; i < NITEM; i += NWORK) {
            const int b     = i & (NB - 1);
            const int chunk = i >> 5;

            if (tid == 0) {
                int cur;
                do {
                    asm volatile("ld.acquire.gpu.global.s32 %0, [%1];"
                                 : "=r"(cur) : "l"(&g_prog[b]) : "memory");
                    if (cur > chunk) break;
                    __nanosleep(128);
                } while (true);
            }
            __syncthreads();                     // flag acquire -> tile loads

            const float* src = g_hs + ((size_t)b * NS + (size_t)chunk * CHUNK) * ND;
            if (tid < 128) {
#pragma unroll
                for (int q = 0; q < 2; q++)
                    ((float4*)tile)[tid + 128 * q] = ((const float4*)src)[tid + 128 * q];
            }
            __syncthreads();

            if (tid < 128) {
                float* orow = out + ((size_t)b * NS + (size_t)chunk * CHUNK) * NC;
#pragma unroll 2
                for (int r = 0; r < CHUNK; r++) {
                    const ulonglong2* hr = (const ulonglong2*)(tile + r * ND);
                    uint64_t p0 = pack2(bias0, 0.f), p1 = pack2(0.f, 0.f);
                    uint64_t q0 = pack2(bias1, 0.f), q1 = pack2(0.f, 0.f);
#pragma unroll
                    for (int j = 0; j < 8; j++) {
                        ulonglong2 hv = hr[j];
                        fma2(p0, hv.x, wv0[2 * j]);
                        fma2(p1, hv.y, wv0[2 * j + 1]);
                        fma2(q0, hv.x, wv1[2 * j]);
                        fma2(q1, hv.y, wv1[2 * j + 1]);
                    }
                    float lo, hi, r0, r1;
                    unpack2(lo, hi, add2(p0, p1)); r0 = lo + hi;
                    unpack2(lo, hi, add2(q0, q1)); r1 = lo + hi;
                    orow[(size_t)r * NC + c0] = r0;
                    orow[(size_t)r * NC + c1] = r1;
                }
            }
            __syncthreads();                     // tile reuse guard
        }
    }
}

extern "C" void kernel_launch(void* const* d_in, const int* in_sizes, int n_in,
                              void* d_out, int out_size)
{
    const float* x      = (const float*)d_in[0];
    const float* bos    = (const float*)d_in[1];
    const float* W_in   = (const float*)d_in[2];
    const float* b_in   = (const float*)d_in[3];
    const float* Wx     = (const float*)d_in[4];
    const float* Wh     = (const float*)d_in[5];
    const float* b_lstm = (const float*)d_in[6];
    const float* W_out  = (const float*)d_in[7];
    const float* b_out  = (const float*)d_in[8];

    init_kernel<<<1, 32>>>();
    fused_kernel<<<148, NT>>>(x, bos, W_in, b_in, Wx, Wh, b_lstm,
                              W_out, b_out, (float*)d_out);
}

// round 15
// speedup vs baseline: 1.0029x; 1.0029x over previous
#include <cuda_runtime.h>
#include <cstdint>

#define NB 32        // batch
#define NS 8192      // seq len
#define ND 32        // hidden dim
#define NG 128       // 4*ND gates
#define NC 256       // output cats
#define CHUNK 32     // steps per progress publish
#define NCHUNK (NS / CHUNK)        // 256
#define NWORK 116                  // worker blocks (148 - 32)
#define NITEM (NB * NCHUNK)        // 8192 work items
#define NT 160                     // threads per block
#define ROWB (ND * 4)              // 128 bytes per ring row
#define HALFB (CHUNK * ROWB)       // 4096 bytes per ring half

// h history (B, S, D) fp32 = 33.5 MB + progress flags
__device__ float g_hs[NB * NS * ND];
__device__ int   g_prog[NB];

__device__ __forceinline__ float tanh_fast(float x) {
    float y;
    asm("tanh.approx.f32 %0, %1;" : "=f"(y) : "f"(x));
    return y;
}
__device__ __forceinline__ uint64_t pack2(float lo, float hi) {
    uint64_t r;
    asm("mov.b64 %0, {%1, %2};" : "=l"(r) : "f"(lo), "f"(hi));
    return r;
}
__device__ __forceinline__ void unpack2(float& lo, float& hi, uint64_t v) {
    asm("mov.b64 {%0, %1}, %2;" : "=f"(lo), "=f"(hi) : "l"(v));
}
__device__ __forceinline__ void fma2(uint64_t& acc, uint64_t a, uint64_t b) {
    asm("fma.rn.f32x2 %0, %1, %2, %0;" : "+l"(acc) : "l"(a), "l"(b));
}
__device__ __forceinline__ uint64_t add2(uint64_t a, uint64_t b) {
    uint64_t r;
    asm("add.rn.f32x2 %0, %1, %2;" : "=l"(r) : "l"(a), "l"(b));
    return r;
}
__device__ __forceinline__ void bar_sync(int id, int cnt) {
    asm volatile("bar.sync %0, %1;" :: "r"(id), "r"(cnt) : "memory");
}
__device__ __forceinline__ uint32_t smem_u32(const void* p) {
    uint32_t a;
    asm("{ .reg .u64 t; cvta.to.shared.u64 t, %1; cvt.u32.u64 %0, t; }"
        : "=r"(a) : "l"(p));
    return a;
}
__device__ __forceinline__ void publish(uint32_t addr, float act, int tag) {
    asm volatile("st.volatile.shared.v2.b32 [%0], {%1, %2};"
                 :: "r"(addr), "f"(act), "r"(tag) : "memory");
}

__global__ void init_kernel() {
    if (threadIdx.x < NB) g_prog[threadIdx.x] = 0;
}

// grid = 148 x 160.
//   blocks 0..31: LSTM scan. Warps 0-3 = gates (i,f,g,o), lane = hidden dim.
//     NO per-step barrier: activations exchanged as {act, step-tag} 8-byte
//     volatile smem slots, double-buffered by step parity; consumers poll
//     until all 4 tags match (data flow itself bounds skew to 1 step, which
//     makes parity reuse safe). Warp 0's 64-slot h ring feeds the mover
//     (warp 4), synced once per 32-step chunk via named bar 2 (64 thr).
//   blocks 32..147: persistent epilogue workers.
__global__ void __launch_bounds__(NT, 1) fused_kernel(
    const float* __restrict__ x,      // (B, S)
    const float* __restrict__ bos,    // (D)
    const float* __restrict__ W_in,   // (1, D)
    const float* __restrict__ b_in,   // (D)
    const float* __restrict__ Wx,     // (D, 4D)
    const float* __restrict__ Wh,     // (D, 4D)
    const float* __restrict__ b_lstm, // (4D)
    const float* __restrict__ W_out,  // (D, C)
    const float* __restrict__ b_out,  // (C)
    float* __restrict__ out)          // (B, S, C)
{
    const int bid = blockIdx.x;
    const int tid = threadIdx.x;

    if (bid < NB) {
        // ───────────────────────── scan block ─────────────────────────
        const int b = bid;

        __shared__ uint64_t gslot[2][4][32];   // [parity][gate][lane]={act,tag} 2KB
        __shared__ float    rings[4][64][ND];  // per-warp h rings            32KB

        if (tid < 128) {
            // ── scan warps ──
            const int w = tid >> 5;     // gate: 0=i 1=f 2=g 3=o
            const int l = tid & 31;     // hidden dim
            const int k = tid;          // gate column
            const bool sig = (w != 2);

            const float ws = sig ? 0.5f : 1.0f;
            uint64_t whp[16];
#pragma unroll
            for (int j = 0; j < 16; j++)
                whp[j] = pack2(ws * Wh[(2 * j) * NG + k],
                               ws * Wh[(2 * j + 1) * NG + k]);

            float u = 0.f, v = 0.f, z0 = 0.f;
#pragma unroll
            for (int d = 0; d < ND; d++) {
                float wx = Wx[d * NG + k];
                u  = fmaf(W_in[d], wx, u);
                v  = fmaf(b_in[d], wx, v);
                z0 = fmaf(bos[d],  wx, z0);
            }
            float bl = b_lstm[k];
            v  = ws * (v + bl);
            z0 = ws * (z0 + bl);
            u *= ws;

            const uint32_t ringw = smem_u32(&rings[w][0][0]);
            const uint32_t gb0   = smem_u32(gslot) + (uint32_t)l * 8;  // parity 0
            const uint32_t gb1   = gb0 + 1024;                         // parity 1
            const uint32_t own0  = gb0 + (uint32_t)w * 256;
            const uint32_t own1  = gb1 + (uint32_t)w * 256;

            // sentinel tag in parity-1 slot; act(0) into parity-0 slot
            publish(own1, 0.f, -1);
            {
                float t0 = tanh_fast(z0);
                float a0 = sig ? fmaf(0.5f, t0, 0.5f) : t0;
                publish(own0, a0, 0);
            }
            bar_sync(1, 128);          // sentinels + act(0) visible to all

            float c = 0.f;
            const float* xb = x + (size_t)b * NS;
            float xv_cur = __ldg(xb + l);           // chunk 0's x

            // J2 = compile-time step-in-group; runtime adds hoisted per group
#define STEP(J2) do {                                                        \
        const int s_ = sj + (J2);                                            \
        float xn = __shfl_sync(0xffffffffu, xv, jj + (J2));                  \
        float zbase = fmaf(xn, u, v);                                        \
        const uint32_t pa = (((J2) & 1) ? gb1 : gb0);                        \
        float i_, f_, g_, o_;                                                \
        uint32_t t0, t1, t2, t3;                                             \
        for (;;) {                                                           \
            asm volatile("ld.volatile.shared.v2.b32 {%0,%1}, [%2];"          \
                         : "=f"(i_), "=r"(t0) : "r"(pa + 0) : "memory");     \
            asm volatile("ld.volatile.shared.v2.b32 {%0,%1}, [%2];"          \
                         : "=f"(f_), "=r"(t1) : "r"(pa + 256) : "memory");   \
            asm volatile("ld.volatile.shared.v2.b32 {%0,%1}, [%2];"          \
                         : "=f"(g_), "=r"(t2) : "r"(pa + 512) : "memory");   \
            asm volatile("ld.volatile.shared.v2.b32 {%0,%1}, [%2];"          \
                         : "=f"(o_), "=r"(t3) : "r"(pa + 768) : "memory");   \
            int ok = (t0 == (uint32_t)s_) & (t1 == (uint32_t)s_) &           \
                     (t2 == (uint32_t)s_) & (t3 == (uint32_t)s_);            \
            if (__all_sync(0xffffffffu, ok)) break;                          \
        }                                                                    \
        c = fmaf(f_, c, i_ * g_);                                            \
        float h = o_ * tanh_fast(c);                                         \
        const uint32_t hrow = rbj + (J2) * ROWB;                             \
        asm volatile("st.shared.f32 [%0], %1;"                               \
                     :: "r"(hrow + l * 4), "f"(h) : "memory");               \
        uint64_t hp[16];                                                     \
        _Pragma("unroll")                                                    \
        for (int j = 0; j < 8; j++)                                          \
            asm volatile("ld.shared.v2.u64 {%0,%1}, [%2];"                   \
                         : "=l"(hp[2 * j]), "=l"(hp[2 * j + 1])              \
                         : "r"(hrow + j * 16));                              \
        uint64_t a0 = pack2(zbase, 0.f), a1 = pack2(0.f, 0.f);               \
        uint64_t a2 = pack2(0.f, 0.f),   a3 = pack2(0.f, 0.f);               \
        _Pragma("unroll")                                                    \
        for (int j = 0; j < 4; j++) {                                        \
            fma2(a0, hp[4 * j + 0], whp[4 * j + 0]);                         \
            fma2(a1, hp[4 * j + 1], whp[4 * j + 1]);                         \
            fma2(a2, hp[4 * j + 2], whp[4 * j + 2]);                         \
            fma2(a3, hp[4 * j + 3], whp[4 * j + 3]);                         \
        }                                                                    \
        float lo, hi;                                                        \
        unpack2(lo, hi, add2(add2(a0, a1), add2(a2, a3)));                   \
        float z = lo + hi;                                                   \
        float t = tanh_fast(z);                                              \
        float act = sig ? fmaf(0.5f, t, 0.5f) : t;                           \
        publish(((J2) & 1) ? own0 : own1, act, s_ + 1);                      \
    } while (0)

            for (int n = 0; n < NCHUNK; n++) {
                const uint32_t rb = ringw + (uint32_t)(n & 1) * HALFB;
                const int s0 = n * CHUNK;
                const float xv = xv_cur;
                xv_cur = __ldg(xb + ((n + 1) & (NCHUNK - 1)) * CHUNK + l);
#pragma unroll 1
                for (int jj = 0; jj < CHUNK; jj += 8) {
                    const int      sj  = s0 + jj;
                    const uint32_t rbj = rb + (uint32_t)jj * ROWB;
                    STEP(0); STEP(1); STEP(2); STEP(3);
                    STEP(4); STEP(5); STEP(6); STEP(7);
                }
                if (w == 0) bar_sync(2, 64);     // hand chunk n to mover
            }
#undef STEP
        } else {
            // ── mover warp (warp 4) ──
            const int l = tid - 128;
            float* hs_b = g_hs + (size_t)b * NS * ND;

            for (int n = 0; n < NCHUNK; n++) {
                bar_sync(2, 64);                 // wait: warp 0 finished chunk n
                const float4* src =
                    (const float4*)&rings[0][(n & 1) * CHUNK][0];
                float4* dst = (float4*)(hs_b + (size_t)n * CHUNK * ND);
#pragma unroll
                for (int q = 0; q < 8; q++)
                    dst[l + 32 * q] = src[l + 32 * q];
                if (l == 0) {
                    __threadfence();
                    asm volatile("st.global.release.gpu.s32 [%0], %1;"
                                 :: "l"(&g_prog[b]), "r"(n + 1) : "memory");
                }
            }
        }
    } else {
        // ─────────────────────── worker block ───────────────────────
        const int wkr = bid - NB;
        __shared__ float tile[CHUNK * ND];       // 4 KB h tile

        const int c0 = tid, c1 = tid + 128;      // valid for tid < 128
        uint64_t wv0[16], wv1[16];
        float bias0 = 0.f, bias1 = 0.f;
        if (tid < 128) {
#pragma unroll
            for (int j = 0; j < 16; j++) {
                wv0[j] = pack2(W_out[(2 * j) * NC + c0], W_out[(2 * j + 1) * NC + c0]);
                wv1[j] = pack2(W_out[(2 * j) * NC + c1], W_out[(2 * j + 1) * NC + c1]);
            }
            bias0 = b_out[c0];
            bias1 = b_out[c1];
        }

        for (int i = wkr; i < NITEM; i += NWORK) {
            const int b     = i & (NB - 1);
            const int chunk = i >> 5;

            if (tid == 0) {
                int cur;
                do {
                    asm volatile("ld.acquire.gpu.global.s32 %0, [%1];"
                                 : "=r"(cur) : "l"(&g_prog[b]) : "memory");
                    if (cur > chunk) break;
                    __nanosleep(128);
                } while (true);
            }
            __syncthreads();                     // flag acquire -> tile loads

            const float* src = g_hs + ((size_t)b * NS + (size_t)chunk * CHUNK) * ND;
            if (tid < 128) {
#pragma unroll
                for (int q = 0; q < 2; q++)
                    ((float4*)tile)[tid + 128 * q] = ((const float4*)src)[tid + 128 * q];
            }
            __syncthreads();

            if (tid < 128) {
                float* orow = out + ((size_t)b * NS + (size_t)chunk * CHUNK) * NC;
#pragma unroll 2
                for (int r = 0; r < CHUNK; r++) {
                    const ulonglong2* hr = (const ulonglong2*)(tile + r * ND);
                    uint64_t p0 = pack2(bias0, 0.f), p1 = pack2(0.f, 0.f);
                    uint64_t q0 = pack2(bias1, 0.f), q1 = pack2(0.f, 0.f);
#pragma unroll
                    for (int j = 0; j < 8; j++) {
                        ulonglong2 hv = hr[j];
                        fma2(p0, hv.x, wv0[2 * j]);
                        fma2(p1, hv.y, wv0[2 * j + 1]);
                        fma2(q0, hv.x, wv1[2 * j]);
                        fma2(q1, hv.y, wv1[2 * j + 1]);
                    }
                    float lo, hi, r0, r1;
                    unpack2(lo, hi, add2(p0, p1)); r0 = lo + hi;
                    unpack2(lo, hi, add2(q0, q1)); r1 = lo + hi;
                    orow[(size_t)r * NC + c0] = r0;
                    orow[(size_t)r * NC + c1] = r1;
                }
            }
            __syncthreads();                     // tile reuse guard
        }
    }
}

extern "C" void kernel_launch(void* const* d_in, const int* in_sizes, int n_in,
                              void* d_out, int out_size)
{
    const float* x      = (const float*)d_in[0];
    const float* bos    = (const float*)d_in[1];
    const float* W_in   = (const float*)d_in[2];
    const float* b_in   = (const float*)d_in[3];
    const float* Wx     = (const float*)d_in[4];
    const float* Wh     = (const float*)d_in[5];
    const float* b_lstm = (const float*)d_in[6];
    const float* W_out  = (const float*)d_in[7];
    const float* b_out  = (const float*)d_in[8];

    init_kernel<<<1, 32>>>();
    fused_kernel<<<148, NT>>>(x, bos, W_in, b_in, Wx, Wh, b_lstm,
                              W_out, b_out, (float*)d_out);
}

// round 16
// speedup vs baseline: 1.3461x; 1.3421x over previous
#include <cuda_runtime.h>
#include <cstdint>

#define NB 32        // batch
#define NS 8192      // seq len
#define ND 32        // hidden dim
#define NG 128       // 4*ND gates
#define NC 256       // output cats
#define CHUNK 32     // steps per progress publish
#define NCHUNK (NS / CHUNK)        // 256
#define NWORK 116                  // worker blocks (148 - 32)
#define NITEM (NB * NCHUNK)        // 8192 work items
#define NT 160                     // threads per block (5 warps in scan blocks)
#define ROWB (ND * 4)              // 128 bytes per ring row
#define HALFB (CHUNK * ROWB)       // 4096 bytes per ring half

// h history (B, S, D) fp32 = 33.5 MB + progress flags
__device__ float g_hs[NB * NS * ND];
__device__ int   g_prog[NB];

__device__ __forceinline__ float tanh_fast(float x) {
    float y;
    asm("tanh.approx.f32 %0, %1;" : "=f"(y) : "f"(x));
    return y;
}
__device__ __forceinline__ uint64_t pack2(float lo, float hi) {
    uint64_t r;
    asm("mov.b64 %0, {%1, %2};" : "=l"(r) : "f"(lo), "f"(hi));
    return r;
}
__device__ __forceinline__ void unpack2(float& lo, float& hi, uint64_t v) {
    asm("mov.b64 {%0, %1}, %2;" : "=f"(lo), "=f"(hi) : "l"(v));
}
__device__ __forceinline__ void fma2(uint64_t& acc, uint64_t a, uint64_t b) {
    asm("fma.rn.f32x2 %0, %1, %2, %0;" : "+l"(acc) : "l"(a), "l"(b));
}
__device__ __forceinline__ uint64_t add2(uint64_t a, uint64_t b) {
    uint64_t r;
    asm("add.rn.f32x2 %0, %1, %2;" : "=l"(r) : "l"(a), "l"(b));
    return r;
}
__device__ __forceinline__ void bar_sync(int id, int cnt) {
    asm volatile("bar.sync %0, %1;" :: "r"(id), "r"(cnt) : "memory");
}
__device__ __forceinline__ void bar_arrive(int id, int cnt) {
    asm volatile("bar.arrive %0, %1;" :: "r"(id), "r"(cnt) : "memory");
}
__device__ __forceinline__ uint32_t smem_u32(const void* p) {
    uint32_t a;
    asm("{ .reg .u64 t; cvta.to.shared.u64 t, %1; cvt.u32.u64 %0, t; }"
        : "=r"(a) : "l"(p));
    return a;
}

__global__ void init_kernel() {
    if (threadIdx.x < NB) g_prog[threadIdx.x] = 0;
}

// grid = 148 x 160.
//   blocks 0..31: LSTM scan. Warps 0-3 = gates (i,f,g,o), lane = hidden dim;
//     per-step sync = named bar 1 (128 threads). EVERY warp owns a private
//     64-slot h ring (uniform code, compile-time offsets, symmetric barrier
//     arrival); warp 0's ring is the mover's source. gbuf transposed
//     [parity][gate][dim]: conflict-free STS + 4 scalar LDS (i,g first).
//     Warp 4 = mover: copies chunk n-1 ring->g_hs while chunk n scans.
//     Chunk boundary: warp0<->mover only, via named bars 2 (ready) / 3 (free);
//     warps 1-3 never stall at boundaries.
//   blocks 32..147: persistent epilogue workers.
__global__ void __launch_bounds__(NT, 1) fused_kernel(
    const float* __restrict__ x,      // (B, S)
    const float* __restrict__ bos,    // (D)
    const float* __restrict__ W_in,   // (1, D)
    const float* __restrict__ b_in,   // (D)
    const float* __restrict__ Wx,     // (D, 4D)
    const float* __restrict__ Wh,     // (D, 4D)
    const float* __restrict__ b_lstm, // (4D)
    const float* __restrict__ W_out,  // (D, C)
    const float* __restrict__ b_out,  // (C)
    float* __restrict__ out)          // (B, S, C)
{
    const int bid = blockIdx.x;
    const int tid = threadIdx.x;

    if (bid < NB) {
        // ───────────────────────── scan block ─────────────────────────
        const int b = bid;

        __shared__ float gbuf[2][4][32];     // [parity][gate][dim]  1 KB
        __shared__ float rings[4][64][ND];   // per-warp h rings    32 KB

        if (tid < 128) {
            // ── scan warps ──
            const int w = tid >> 5;     // gate: 0=i 1=f 2=g 3=o
            const int l = tid & 31;     // hidden dim
            const int k = tid;          // gate column
            const bool sig = (w != 2);

            const float ws = sig ? 0.5f : 1.0f;
            uint64_t whp[16];
#pragma unroll
            for (int j = 0; j < 16; j++)
                whp[j] = pack2(ws * Wh[(2 * j) * NG + k],
                               ws * Wh[(2 * j + 1) * NG + k]);

            float u = 0.f, v = 0.f, z0 = 0.f;
#pragma unroll
            for (int d = 0; d < ND; d++) {
                float wx = Wx[d * NG + k];
                u  = fmaf(W_in[d], wx, u);
                v  = fmaf(b_in[d], wx, v);
                z0 = fmaf(bos[d],  wx, z0);
            }
            float bl = b_lstm[k];
            v  = ws * (v + bl);
            z0 = ws * (z0 + bl);
            u *= ws;

            const uint32_t ringw = smem_u32(&rings[w][0][0]);
            const uint32_t gb    = smem_u32(gbuf);
            const uint32_t ga    = gb + (uint32_t)(w * 32 + l) * 4;  // act store
            const uint32_t gl    = gb + (uint32_t)l * 4;             // gate loads

            // zero slot 63 of own ring (read by chunk 0 step 0)
            asm volatile("st.shared.f32 [%0], %1;"
                         :: "r"(ringw + 63 * ROWB + l * 4), "f"(0.f) : "memory");

            float c = 0.f;
            float zbase = z0;
            const float* xb = x + (size_t)b * NS;
            float xv_cur = __ldg(xb + l);           // chunk 0's x

            // P = gbuf parity, J = step position in chunk (compile-time)
#define STEP(P, J) do {                                                      \
        float xn = __shfl_sync(0xffffffffu, xv, (J));                        \
        const uint32_t rda = ((J) == 0) ? rbp : rb + ((J) - 1) * ROWB;       \
        uint64_t hp[16];                                                     \
        _Pragma("unroll")                                                    \
        for (int j = 0; j < 8; j++)                                          \
            asm volatile("ld.shared.v2.u64 {%0,%1}, [%2];"                   \
                         : "=l"(hp[2 * j]), "=l"(hp[2 * j + 1])              \
                         : "r"(rda + j * 16));                               \
        uint64_t a0 = pack2(zbase, 0.f), a1 = pack2(0.f, 0.f);               \
        uint64_t a2 = pack2(0.f, 0.f),   a3 = pack2(0.f, 0.f);               \
        _Pragma("unroll")                                                    \
        for (int j = 0; j < 4; j++) {                                        \
            fma2(a0, hp[4 * j + 0], whp[4 * j + 0]);                         \
            fma2(a1, hp[4 * j + 1], whp[4 * j + 1]);                         \
            fma2(a2, hp[4 * j + 2], whp[4 * j + 2]);                         \
            fma2(a3, hp[4 * j + 3], whp[4 * j + 3]);                         \
        }                                                                    \
        float lo, hi;                                                        \
        unpack2(lo, hi, add2(add2(a0, a1), add2(a2, a3)));                   \
        float z = lo + hi;                                                   \
        float t = tanh_fast(z);                                              \
        float act = sig ? fmaf(0.5f, t, 0.5f) : t;                           \
        asm volatile("st.shared.f32 [%0], %1;"                               \
                     :: "r"(ga + (P) * 512), "f"(act) : "memory");           \
        zbase = fmaf(xn, u, v);                                              \
        bar_sync(1, 128);                                                    \
        float i_, g_, f_, o_;                                                \
        asm volatile("ld.shared.f32 %0, [%1];" : "=f"(i_)                    \
                     : "r"(gl + (P) * 512 + 0));                             \
        asm volatile("ld.shared.f32 %0, [%1];" : "=f"(g_)                    \
                     : "r"(gl + (P) * 512 + 256));                           \
        asm volatile("ld.shared.f32 %0, [%1];" : "=f"(f_)                    \
                     : "r"(gl + (P) * 512 + 128));                           \
        asm volatile("ld.shared.f32 %0, [%1];" : "=f"(o_)                    \
                     : "r"(gl + (P) * 512 + 384));                           \
        c = fmaf(f_, c, i_ * g_);                                            \
        float h = o_ * tanh_fast(c);                                         \
        asm volatile("st.shared.f32 [%0], %1;"                               \
                     :: "r"(rb + (J) * ROWB + l * 4), "f"(h) : "memory");    \
    } while (0)

            for (int n = 0; n < NCHUNK; n++) {
                const uint32_t rb  = ringw + (uint32_t)(n & 1) * HALFB;
                const uint32_t rbp = ringw + (uint32_t)((n & 1) ^ 1) * HALFB
                                   + 31 * ROWB;
                // warp 0 must not rewrite a ring half the mover hasn't copied
                if (w == 0 && n >= 2) bar_sync(3, 64);
                const float xv = xv_cur;
                // prefetch next chunk's x a full chunk ahead (wraps, unused)
                xv_cur = __ldg(xb + ((n + 1) & (NCHUNK - 1)) * CHUNK + l);
#pragma unroll
                for (int jj = 0; jj < CHUNK; jj += 4) {
                    STEP(0, jj + 0);
                    STEP(1, jj + 1);
                    STEP(0, jj + 2);
                    STEP(1, jj + 3);
                }
                if (w == 0) bar_arrive(2, 64);   // chunk n ready for mover
            }
#undef STEP
        } else {
            // ── mover warp (warp 4) ──
            const int l = tid - 128;
            float* hs_b = g_hs + (size_t)b * NS * ND;

            for (int n = 0; n < NCHUNK; n++) {
                bar_sync(2, 64);                 // wait: warp 0 finished chunk n
                const float4* src =
                    (const float4*)&rings[0][(n & 1) * CHUNK][0];
                float4* dst = (float4*)(hs_b + (size_t)n * CHUNK * ND);
#pragma unroll
                for (int q = 0; q < 8; q++)
                    dst[l + 32 * q] = src[l + 32 * q];
                if (l == 0) {
                    __threadfence();
                    asm volatile("st.global.release.gpu.s32 [%0], %1;"
                                 :: "l"(&g_prog[b]), "r"(n + 1) : "memory");
                }
                bar_arrive(3, 64);               // ring half freed
            }
        }
    } else {
        // ─────────────────────── worker block ───────────────────────
        const int wkr = bid - NB;
        __shared__ float tile[CHUNK * ND];       // 4 KB h tile

        const int c0 = tid, c1 = tid + 128;      // valid for tid < 128
        uint64_t wv0[16], wv1[16];
        float bias0 = 0.f, bias1 = 0.f;
        if (tid < 128) {
#pragma unroll
            for (int j = 0; j < 16; j++) {
                wv0[j] = pack2(W_out[(2 * j) * NC + c0], W_out[(2 * j + 1) * NC + c0]);
                wv1[j] = pack2(W_out[(2 * j) * NC + c1], W_out[(2 * j + 1) * NC + c1]);
            }
            bias0 = b_out[c0];
            bias1 = b_out[c1];
        }

        for (int i = wkr; i < NITEM; i += NWORK) {
            const int b     = i & (NB - 1);
            const int chunk = i >> 5;

            if (tid == 0) {
                int cur;
                do {
                    asm volatile("ld.acquire.gpu.global.s32 %0, [%1];"
                                 : "=r"(cur) : "l"(&g_prog[b]) : "memory");
                    if (cur > chunk) break;
                    __nanosleep(128);
                } while (true);
            }
            __syncthreads();                     // flag acquire -> tile loads

            const float* src = g_hs + ((size_t)b * NS + (size_t)chunk * CHUNK) * ND;
            if (tid < 128) {
#pragma unroll
                for (int q = 0; q < 2; q++)
                    ((float4*)tile)[tid + 128 * q] = ((const float4*)src)[tid + 128 * q];
            }
            __syncthreads();

            if (tid < 128) {
                float* orow = out + ((size_t)b * NS + (size_t)chunk * CHUNK) * NC;
#pragma unroll 2
                for (int r = 0; r < CHUNK; r++) {
                    const ulonglong2* hr = (const ulonglong2*)(tile + r * ND);
                    uint64_t p0 = pack2(bias0, 0.f), p1 = pack2(0.f, 0.f);
                    uint64_t q0 = pack2(bias1, 0.f), q1 = pack2(0.f, 0.f);
#pragma unroll
                    for (int j = 0; j < 8; j++) {
                        ulonglong2 hv = hr[j];
                        fma2(p0, hv.x, wv0[2 * j]);
                        fma2(p1, hv.y, wv0[2 * j + 1]);
                        fma2(q0, hv.x, wv1[2 * j]);
                        fma2(q1, hv.y, wv1[2 * j + 1]);
                    }
                    float lo, hi, r0, r1;
                    unpack2(lo, hi, add2(p0, p1)); r0 = lo + hi;
                    unpack2(lo, hi, add2(q0, q1)); r1 = lo + hi;
                    orow[(size_t)r * NC + c0] = r0;
                    orow[(size_t)r * NC + c1] = r1;
                }
            }
            __syncthreads();                     // tile reuse guard
        }
    }
}

extern "C" void kernel_launch(void* const* d_in, const int* in_sizes, int n_in,
                              void* d_out, int out_size)
{
    const float* x      = (const float*)d_in[0];
    const float* bos    = (const float*)d_in[1];
    const float* W_in   = (const float*)d_in[2];
    const float* b_in   = (const float*)d_in[3];
    const float* Wx     = (const float*)d_in[4];
    const float* Wh     = (const float*)d_in[5];
    const float* b_lstm = (const float*)d_in[6];
    const float* W_out  = (const float*)d_in[7];
    const float* b_out  = (const float*)d_in[8];

    init_kernel<<<1, 32>>>();
    fused_kernel<<<148, NT>>>(x, bos, W_in, b_in, Wx, Wh, b_lstm,
                              W_out, b_out, (float*)d_out);
}

// round 17
// speedup vs baseline: 1.3979x; 1.0385x over previous
#include <cuda_runtime.h>
#include <cstdint>

#define NB 32        // batch
#define NS 8192      // seq len
#define ND 32        // hidden dim
#define NG 128       // 4*ND gates
#define NC 256       // output cats
#define CHUNK 32     // steps per progress publish
#define NCHUNK (NS / CHUNK)        // 256
#define NWORK 116                  // worker blocks (148 - 32)
#define NITEM (NB * NCHUNK)        // 8192 work items
#define NT 160                     // threads per block (5 warps in scan blocks)
#define ROWB (ND * 4)              // 128 bytes per ring row
#define HALFB (CHUNK * ROWB)       // 4096 bytes per ring half

// h history (B, S, D) fp32 = 33.5 MB + progress flags
__device__ float g_hs[NB * NS * ND];
__device__ int   g_prog[NB];

__device__ __forceinline__ float tanh_fast(float x) {
    float y;
    asm("tanh.approx.f32 %0, %1;" : "=f"(y) : "f"(x));
    return y;
}
__device__ __forceinline__ uint64_t pack2(float lo, float hi) {
    uint64_t r;
    asm("mov.b64 %0, {%1, %2};" : "=l"(r) : "f"(lo), "f"(hi));
    return r;
}
__device__ __forceinline__ void unpack2(float& lo, float& hi, uint64_t v) {
    asm("mov.b64 {%0, %1}, %2;" : "=f"(lo), "=f"(hi) : "l"(v));
}
__device__ __forceinline__ void fma2(uint64_t& acc, uint64_t a, uint64_t b) {
    asm("fma.rn.f32x2 %0, %1, %2, %0;" : "+l"(acc) : "l"(a), "l"(b));
}
__device__ __forceinline__ uint64_t add2(uint64_t a, uint64_t b) {
    uint64_t r;
    asm("add.rn.f32x2 %0, %1, %2;" : "=l"(r) : "l"(a), "l"(b));
    return r;
}
__device__ __forceinline__ void bar_sync(int id, int cnt) {
    asm volatile("bar.sync %0, %1;" :: "r"(id), "r"(cnt) : "memory");
}
__device__ __forceinline__ void bar_arrive(int id, int cnt) {
    asm volatile("bar.arrive %0, %1;" :: "r"(id), "r"(cnt) : "memory");
}
__device__ __forceinline__ uint32_t smem_u32(const void* p) {
    uint32_t a;
    asm("{ .reg .u64 t; cvta.to.shared.u64 t, %1; cvt.u32.u64 %0, t; }"
        : "=r"(a) : "l"(p));
    return a;
}

__global__ void init_kernel() {
    if (threadIdx.x < NB) g_prog[threadIdx.x] = 0;
}

// grid = 148 x 160.
//   blocks 0..31: LSTM scan. Warps 0-3 = gates (i,f,g,o), lane = hidden dim;
//     per-step sync = named bar 1 (128 threads). Every warp owns a private
//     64-slot h ring; warp 0's ring feeds the mover (warp 4). gbuf transposed
//     [parity][gate][dim]. Step loop = 8-step groups (small hot code, stays
//     in L1.5 I$); previous-row address carried in a register (rd).
//     Chunk boundary: warp0<->mover via named bars 2 (ready) / 3 (free).
//   blocks 32..147: persistent epilogue workers.
__global__ void __launch_bounds__(NT, 1) fused_kernel(
    const float* __restrict__ x,      // (B, S)
    const float* __restrict__ bos,    // (D)
    const float* __restrict__ W_in,   // (1, D)
    const float* __restrict__ b_in,   // (D)
    const float* __restrict__ Wx,     // (D, 4D)
    const float* __restrict__ Wh,     // (D, 4D)
    const float* __restrict__ b_lstm, // (4D)
    const float* __restrict__ W_out,  // (D, C)
    const float* __restrict__ b_out,  // (C)
    float* __restrict__ out)          // (B, S, C)
{
    const int bid = blockIdx.x;
    const int tid = threadIdx.x;

    if (bid < NB) {
        // ───────────────────────── scan block ─────────────────────────
        const int b = bid;

        __shared__ float gbuf[2][4][32];     // [parity][gate][dim]  1 KB
        __shared__ float rings[4][64][ND];   // per-warp h rings    32 KB

        if (tid < 128) {
            // ── scan warps ──
            const int w = tid >> 5;     // gate: 0=i 1=f 2=g 3=o
            const int l = tid & 31;     // hidden dim
            const int k = tid;          // gate column
            const bool sig = (w != 2);

            const float ws = sig ? 0.5f : 1.0f;
            uint64_t whp[16];
#pragma unroll
            for (int j = 0; j < 16; j++)
                whp[j] = pack2(ws * Wh[(2 * j) * NG + k],
                               ws * Wh[(2 * j + 1) * NG + k]);

            float u = 0.f, v = 0.f, z0 = 0.f;
#pragma unroll
            for (int d = 0; d < ND; d++) {
                float wx = Wx[d * NG + k];
                u  = fmaf(W_in[d], wx, u);
                v  = fmaf(b_in[d], wx, v);
                z0 = fmaf(bos[d],  wx, z0);
            }
            float bl = b_lstm[k];
            v  = ws * (v + bl);
            z0 = ws * (z0 + bl);
            u *= ws;

            const uint32_t ringw = smem_u32(&rings[w][0][0]);
            const uint32_t gb    = smem_u32(gbuf);
            const uint32_t ga    = gb + (uint32_t)(w * 32 + l) * 4;  // act store
            const uint32_t gl    = gb + (uint32_t)l * 4;             // gate loads

            // zero slot 63 of own ring (read by chunk 0 step 0)
            asm volatile("st.shared.f32 [%0], %1;"
                         :: "r"(ringw + 63 * ROWB + l * 4), "f"(0.f) : "memory");

            float c = 0.f;
            float zbase = z0;
            uint32_t rd = ringw + 63 * ROWB;        // prev-h row (carried)
            const float* xb = x + (size_t)b * NS;
            float xv_cur = __ldg(xb + l);           // chunk 0's x

            // P = gbuf parity, J2 = position in 8-step group (compile-time)
#define STEP(P, J2) do {                                                     \
        float xn = __shfl_sync(0xffffffffu, xv, jj + (J2));                  \
        uint64_t hp[16];                                                     \
        _Pragma("unroll")                                                    \
        for (int j = 0; j < 8; j++)                                          \
            asm volatile("ld.shared.v2.u64 {%0,%1}, [%2];"                   \
                         : "=l"(hp[2 * j]), "=l"(hp[2 * j + 1])              \
                         : "r"(rd + j * 16));                                \
        uint64_t a0 = pack2(zbase, 0.f), a1 = pack2(0.f, 0.f);               \
        _Pragma("unroll")                                                    \
        for (int j = 0; j < 8; j++) {                                        \
            fma2(a0, hp[2 * j + 0], whp[2 * j + 0]);                         \
            fma2(a1, hp[2 * j + 1], whp[2 * j + 1]);                         \
        }                                                                    \
        float lo, hi;                                                        \
        unpack2(lo, hi, add2(a0, a1));                                       \
        float z = lo + hi;                                                   \
        float t = tanh_fast(z);                                              \
        float act = sig ? fmaf(0.5f, t, 0.5f) : t;                           \
        asm volatile("st.shared.f32 [%0], %1;"                               \
                     :: "r"(ga + (P) * 512), "f"(act) : "memory");           \
        zbase = fmaf(xn, u, v);                                              \
        bar_sync(1, 128);                                                    \
        float i_, g_, f_, o_;                                                \
        asm volatile("ld.shared.f32 %0, [%1];" : "=f"(i_)                    \
                     : "r"(gl + (P) * 512 + 0));                             \
        asm volatile("ld.shared.f32 %0, [%1];" : "=f"(g_)                    \
                     : "r"(gl + (P) * 512 + 256));                           \
        asm volatile("ld.shared.f32 %0, [%1];" : "=f"(f_)                    \
                     : "r"(gl + (P) * 512 + 128));                           \
        asm volatile("ld.shared.f32 %0, [%1];" : "=f"(o_)                    \
                     : "r"(gl + (P) * 512 + 384));                           \
        c = fmaf(f_, c, i_ * g_);                                            \
        float h = o_ * tanh_fast(c);                                         \
        const uint32_t wr_ = wrj + (J2) * ROWB;                              \
        asm volatile("st.shared.f32 [%0], %1;"                               \
                     :: "r"(wr_ + l * 4), "f"(h) : "memory");                \
        rd = wr_;                                                            \
    } while (0)

            for (int n = 0; n < NCHUNK; n++) {
                const uint32_t rb = ringw + (uint32_t)(n & 1) * HALFB;
                // warp 0 must not rewrite a ring half the mover hasn't copied
                if (w == 0 && n >= 2) bar_sync(3, 64);
                const float xv = xv_cur;
                // prefetch next chunk's x a full chunk ahead (wraps, unused)
                xv_cur = __ldg(xb + ((n + 1) & (NCHUNK - 1)) * CHUNK + l);
#pragma unroll 1
                for (int jj = 0; jj < CHUNK; jj += 8) {
                    const uint32_t wrj = rb + (uint32_t)jj * ROWB;
                    STEP(0, 0); STEP(1, 1); STEP(0, 2); STEP(1, 3);
                    STEP(0, 4); STEP(1, 5); STEP(0, 6); STEP(1, 7);
                }
                if (w == 0) bar_arrive(2, 64);   // chunk n ready for mover
            }
#undef STEP
        } else {
            // ── mover warp (warp 4) ──
            const int l = tid - 128;
            float* hs_b = g_hs + (size_t)b * NS * ND;

            for (int n = 0; n < NCHUNK; n++) {
                bar_sync(2, 64);                 // wait: warp 0 finished chunk n
                const float4* src =
                    (const float4*)&rings[0][(n & 1) * CHUNK][0];
                float4* dst = (float4*)(hs_b + (size_t)n * CHUNK * ND);
#pragma unroll
                for (int q = 0; q < 8; q++)
                    dst[l + 32 * q] = src[l + 32 * q];
                if (l == 0) {
                    __threadfence();
                    asm volatile("st.global.release.gpu.s32 [%0], %1;"
                                 :: "l"(&g_prog[b]), "r"(n + 1) : "memory");
                }
                bar_arrive(3, 64);               // ring half freed
            }
        }
    } else {
        // ─────────────────────── worker block ───────────────────────
        const int wkr = bid - NB;
        __shared__ float tile[CHUNK * ND];       // 4 KB h tile

        const int c0 = tid, c1 = tid + 128;      // valid for tid < 128
        uint64_t wv0[16], wv1[16];
        float bias0 = 0.f, bias1 = 0.f;
        if (tid < 128) {
#pragma unroll
            for (int j = 0; j < 16; j++) {
                wv0[j] = pack2(W_out[(2 * j) * NC + c0], W_out[(2 * j + 1) * NC + c0]);
                wv1[j] = pack2(W_out[(2 * j) * NC + c1], W_out[(2 * j + 1) * NC + c1]);
            }
            bias0 = b_out[c0];
            bias1 = b_out[c1];
        }

        for (int i = wkr; i < NITEM; i += NWORK) {
            const int b     = i & (NB - 1);
            const int chunk = i >> 5;

            if (tid == 0) {
                int cur;
                do {
                    asm volatile("ld.acquire.gpu.global.s32 %0, [%1];"
                                 : "=r"(cur) : "l"(&g_prog[b]) : "memory");
                    if (cur > chunk) break;
                    __nanosleep(128);
                } while (true);
            }
            __syncthreads();                     // flag acquire -> tile loads

            const float* src = g_hs + ((size_t)b * NS + (size_t)chunk * CHUNK) * ND;
            if (tid < 128) {
#pragma unroll
                for (int q = 0; q < 2; q++)
                    ((float4*)tile)[tid + 128 * q] = ((const float4*)src)[tid + 128 * q];
            }
            __syncthreads();

            if (tid < 128) {
                float* orow = out + ((size_t)b * NS + (size_t)chunk * CHUNK) * NC;
#pragma unroll 2
                for (int r = 0; r < CHUNK; r++) {
                    const ulonglong2* hr = (const ulonglong2*)(tile + r * ND);
                    uint64_t p0 = pack2(bias0, 0.f), p1 = pack2(0.f, 0.f);
                    uint64_t q0 = pack2(bias1, 0.f), q1 = pack2(0.f, 0.f);
#pragma unroll
                    for (int j = 0; j < 8; j++) {
                        ulonglong2 hv = hr[j];
                        fma2(p0, hv.x, wv0[2 * j]);
                        fma2(p1, hv.y, wv0[2 * j + 1]);
                        fma2(q0, hv.x, wv1[2 * j]);
                        fma2(q1, hv.y, wv1[2 * j + 1]);
                    }
                    float lo, hi, r0, r1;
                    unpack2(lo, hi, add2(p0, p1)); r0 = lo + hi;
                    unpack2(lo, hi, add2(q0, q1)); r1 = lo + hi;
                    orow[(size_t)r * NC + c0] = r0;
                    orow[(size_t)r * NC + c1] = r1;
                }
            }
            __syncthreads();                     // tile reuse guard
        }
    }
}

extern "C" void kernel_launch(void* const* d_in, const int* in_sizes, int n_in,
                              void* d_out, int out_size)
{
    const float* x      = (const float*)d_in[0];
    const float* bos    = (const float*)d_in[1];
    const float* W_in   = (const float*)d_in[2];
    const float* b_in   = (const float*)d_in[3];
    const float* Wx     = (const float*)d_in[4];
    const float* Wh     = (const float*)d_in[5];
    const float* b_lstm = (const float*)d_in[6];
    const float* W_out  = (const float*)d_in[7];
    const float* b_out  = (const float*)d_in[8];

    init_kernel<<<1, 32>>>();
    fused_kernel<<<148, NT>>>(x, bos, W_in, b_in, Wx, Wh, b_lstm,
                              W_out, b_out, (float*)d_out);
}